// round 9
// baseline (speedup 1.0000x reference)
#include <cuda_runtime.h>
#include <cuda_bf16.h>

#define MATSIZE 512
#define DSZ 10
#define NR (MATSIZE - 2 * DSZ)          // 492 outputs per batch
#define TSPLIT 6
#define TPB (NR / TSPLIT)               // 82 outputs per block
#define ROWS_USED (TPB + DSZ)           // 92 band rows consumed per block
#define ROWS_PAD 96                     // 8 warps * 12 rows loaded (pad rows unused)
#define NLOAD 12                        // rows per thread, batched -> MLP = 12
#define BAND_W 19                       // cols r+2 .. r+20 (all that is ever read)
#define BSTRIDE 21                      // gcd(21,32)=1 -> conflict-free
#define W_STRIDE 11                     // gcd(11,32)=1 -> conflict-free
#define ROW_PITCH (MATSIZE + 1)         // idx(r, r+2+lane) = r*513 + 2 + lane

__global__ __launch_bounds__(256)
void tad_insulation_kernel(const float* __restrict__ x, float* __restrict__ out) {
    const int b     = blockIdx.x;       // batch
    const int split = blockIdx.y;       // t-range sixth
    const int t0    = split * TPB;

    __shared__ float band[ROWS_PAD * BSTRIDE];    // 8064 B
    __shared__ float wsum[ROWS_USED * W_STRIDE];  // 4048 B

    const int tid  = threadIdx.x;
    const int lane = tid & 31;
    const int warp = tid >> 5;

    // ---- Phase 1: load diagonal band rows r = t0+warp+8i (i=0..11), cols r+2+lane ----
    // 12 loads batched off ONE base pointer with compile-time immediate offsets,
    // all issued before any STS -> MLP = 12 per thread. 1536 blocks of 8 warps:
    // wave 1 runs at 8 blocks/SM = 64 warps/SM (100% theoretical occupancy),
    // remainder is a fine-grained work-stealing tail. Only the 19 useful lanes
    // load. All addresses provably in-bounds: max r = 410+7+88 = 505,
    // max idx = 505*513 + 20 = 259,085 < 262,144 per batch.
    {
        const bool active = (lane < BAND_W);
        const float* __restrict__ p =
            x + (size_t)b * MATSIZE * MATSIZE
              + (size_t)(t0 + warp) * ROW_PITCH + 2 + lane;
        if (active) {
            float v[NLOAD];
            #pragma unroll
            for (int i = 0; i < NLOAD; i++)
                v[i] = p[(size_t)i * 8 * ROW_PITCH];     // imm offsets, back-to-back LDG
            #pragma unroll
            for (int i = 0; i < NLOAD; i++)
                band[(warp + 8 * i) * BSTRIDE + lane] = v[i];
        }
    }
    __syncthreads();

    // ---- Phase 2: per-row sliding window sums W[lr][k] = sum_{j<10} band[lr][k+j] ----
    if (tid < ROWS_USED) {
        const float* bp = &band[tid * BSTRIDE];      // conflict-free (stride 21)
        float s = 0.0f;
        #pragma unroll
        for (int j = 0; j < DSZ; j++) s += bp[j];
        float* wp = &wsum[tid * W_STRIDE];
        wp[0] = s;
        #pragma unroll
        for (int k = 1; k < DSZ; k++) {
            s += bp[k + DSZ - 1] - bp[k - 1];
            wp[k] = s;
        }
    }
    __syncthreads();

    // ---- Phase 3: out[t] = (1/100) * sum_{i<10} W[t+i][9-i] ----
    if (tid < TPB) {
        float s = 0.0f;
        #pragma unroll
        for (int i = 0; i < DSZ; i++)
            s += wsum[(tid + i) * W_STRIDE + (DSZ - 1 - i)];
        out[b * NR + t0 + tid] = s * (1.0f / (DSZ * DSZ));
    }
}

extern "C" void kernel_launch(void* const* d_in, const int* in_sizes, int n_in,
                              void* d_out, int out_size) {
    (void)in_sizes; (void)n_in; (void)out_size;
    const float* x = (const float*)d_in[0];
    float* out = (float*)d_out;
    dim3 grid(256, TSPLIT);
    tad_insulation_kernel<<<grid, 256>>>(x, out);
}